// round 5
// baseline (speedup 1.0000x reference)
#include <cuda_runtime.h>
#include <cuda_fp16.h>
#include <math.h>

#define C_CH 256
#define NBIN 49

// Channels-last fp16 scratch for the 4 FPN levels (B=2 fixed by problem).
__device__ __half g_h0[2 * 200 * 200 * C_CH];
__device__ __half g_h1[2 * 100 * 100 * C_CH];
__device__ __half g_h2[2 * 50  * 50  * C_CH];
__device__ __half g_h3[2 * 25  * 25  * C_CH];

// Fused transpose: [B,C,HW] fp32 -> [B,HW,C] fp16, all 4 levels in ONE launch.
__global__ void transpose_all(const float* __restrict__ f0,
                              const float* __restrict__ f1,
                              const float* __restrict__ f2,
                              const float* __restrict__ f3,
                              int B) {
    __shared__ float tile[32][67];

    const int HWs[4] = {200 * 200, 100 * 100, 50 * 50, 25 * 25};
    int idx = blockIdx.x;
    int l = 0, nPx = 0;
    #pragma unroll
    for (int q = 0; q < 4; ++q) {
        nPx = (HWs[q] + 31) / 32;
        int nb = nPx * (C_CH / 64) * B;
        if (idx < nb) { l = q; break; }
        idx -= nb;
    }
    int HW = HWs[l];
    const float* in = (l == 0) ? f0 : (l == 1) ? f1 : (l == 2) ? f2 : f3;
    __half* outp    = (l == 0) ? g_h0 : (l == 1) ? g_h1 : (l == 2) ? g_h2 : g_h3;

    int pt = idx % nPx;
    int r  = idx / nPx;
    int cg = r % (C_CH / 64);
    int b  = r / (C_CH / 64);

    int p0 = pt * 32;
    int c0 = cg * 64;
    const float* ib = in   + (size_t)b * C_CH * HW;
    __half*      ob = outp + (size_t)b * C_CH * HW;
    int tx = threadIdx.x, ty = threadIdx.y;

    int p = p0 + tx;
    #pragma unroll
    for (int i = ty; i < 64; i += 8)
        tile[tx][i] = (p < HW) ? __ldcs(&ib[(size_t)(c0 + i) * HW + p]) : 0.0f;
    __syncthreads();
    #pragma unroll
    for (int i = ty; i < 32; i += 8) {
        int pw = p0 + i;
        if (pw < HW) {
            __half2 h = __halves2half2(__float2half_rn(tile[i][2 * tx]),
                                       __float2half_rn(tile[i][2 * tx + 1]));
            ((__half2*)(ob + (size_t)pw * C_CH + c0))[tx] = h;
        }
    }
}

// One 64-thread block per (box, output-row). Warp sy (0/1) owns y-sample sy.
// Lane owns 8 channels {8*lane .. 8*lane+7} via one uint4 (LDG.128) per tap.
// Per bin, each warp issues 8 independent LDG.128 (2 x-sample groups x 4 taps),
// accumulates the 8-tap chain in half2, and parks packed partials in smem.
// Cross-warp fp32 sum happens once at the coalesced writeout.
__global__ __launch_bounds__(64) void roi_main(const float* __restrict__ props,
                                               float* __restrict__ out,
                                               int Np) {
    __shared__ unsigned stageH[2][7][128];   // [sy][bx][ch-pair] packed half2
    __shared__ uint4 s_off[28];   // [bxi*4 + g] -> 4 tap offsets (uint4 units)
    __shared__ uint4 s_w[28];     // [bxi*4 + g] -> 4 duplicated-half2 weights
    __shared__ int   s_xlo[14], s_xhi[14];
    __shared__ float s_xfr[14], s_xva[14];
    __shared__ int   s_ylo[2],  s_yhi[2];
    __shared__ float s_yfr[2],  s_yva[2];

    int n  = blockIdx.x;
    int by = blockIdx.y;
    int t  = threadIdx.x;

    float bx0 = props[n * 4 + 0];
    float by0 = props[n * 4 + 1];
    float bx1 = props[n * 4 + 2];
    float by1 = props[n * 4 + 3];

    float s  = sqrtf((bx1 - bx0) * (by1 - by0));
    float lv = floorf(4.0f + log2f(s * (1.0f / 224.0f) + 1e-6f));
    lv = fminf(fmaxf(lv, 2.0f), 5.0f);
    int l = (int)lv - 2;

    int H;
    float scale;
    const __half* fp;
    if      (l == 0) { H = 200; scale = 0.25f;    fp = g_h0; }
    else if (l == 1) { H = 100; scale = 0.125f;   fp = g_h1; }
    else if (l == 2) { H = 50;  scale = 0.0625f;  fp = g_h2; }
    else             { H = 25;  scale = 0.03125f; fp = g_h3; }
    int W = H;
    int bidx = n / Np;

    // Sample prep: threads 0..13 -> x samples, 14..15 -> the 2 y samples of this row.
    if (t < 16) {
        bool isY = (t >= 14);
        int  k   = isY ? (2 * by + (t - 14)) : t;
        float off = (float)(k >> 1) + ((float)(k & 1) + 0.5f) * 0.5f;
        float c0  = (isY ? by0 : bx0) * scale;
        float c1  = (isY ? by1 : bx1) * scale;
        float bin = fmaxf(c1 - c0, 1.0f) * (1.0f / 7.0f);
        float c   = c0 + off * bin;
        float valid = (c >= -1.0f && c <= (float)H) ? 1.0f : 0.0f;
        float cc  = fmaxf(c, 0.0f);
        int   lo0 = (int)floorf(cc);
        bool  edge = (lo0 >= H - 1);
        int lo = edge ? (H - 1) : lo0;
        int hi = edge ? (H - 1) : (lo0 + 1);
        float fr = edge ? 0.0f : (cc - (float)lo0);
        if (isY) { int q = t - 14; s_ylo[q] = lo; s_yhi[q] = hi; s_yfr[q] = fr; s_yva[q] = valid; }
        else     {                 s_xlo[t] = lo; s_xhi[t] = hi; s_xfr[t] = fr; s_xva[t] = valid; }
    }
    __syncthreads();

    // Precompute 112 taps: i = bxi*16 + g*4 + tap; g = (sy,sx) group.
    #pragma unroll
    for (int i = t; i < 112; i += 64) {
        int bxi = i >> 4, r = i & 15, g = r >> 2, tap = r & 3;
        int sy = g >> 1, sx = g & 1;
        int kx = 2 * bxi + sx;
        int row = (tap & 2) ? s_yhi[sy] : s_ylo[sy];
        int x   = (tap & 1) ? s_xhi[kx] : s_xlo[kx];
        float wy = (tap & 2) ? s_yfr[sy] : (1.0f - s_yfr[sy]);
        float wx = (tap & 1) ? s_xfr[kx] : (1.0f - s_xfr[kx]);
        float w  = s_yva[sy] * s_xva[kx] * wy * wx;
        ((unsigned*)s_off)[i] = (unsigned)((row * W + x) * (C_CH / 8));
        unsigned hb = (unsigned)__half_as_ushort(__float2half_rn(w));
        ((unsigned*)s_w)[i] = hb | (hb << 16);
    }
    __syncthreads();

    int sy   = t >> 5;
    int lane = t & 31;
    const uint4* fb = (const uint4*)(fp + (size_t)bidx * H * W * C_CH) + lane;

    #pragma unroll 1
    for (int bxi = 0; bxi < 7; ++bxi) {
        int gb = bxi * 4 + sy * 2;
        uint4 o0 = s_off[gb], o1 = s_off[gb + 1];
        uint4 wq0 = s_w[gb],  wq1 = s_w[gb + 1];

        uint4 v0 = __ldg(fb + o0.x);
        uint4 v1 = __ldg(fb + o0.y);
        uint4 v2 = __ldg(fb + o0.z);
        uint4 v3 = __ldg(fb + o0.w);
        uint4 v4 = __ldg(fb + o1.x);
        uint4 v5 = __ldg(fb + o1.y);
        uint4 v6 = __ldg(fb + o1.z);
        uint4 v7 = __ldg(fb + o1.w);

        __half2 W0 = *reinterpret_cast<const __half2*>(&wq0.x);
        __half2 W1 = *reinterpret_cast<const __half2*>(&wq0.y);
        __half2 W2 = *reinterpret_cast<const __half2*>(&wq0.z);
        __half2 W3 = *reinterpret_cast<const __half2*>(&wq0.w);
        __half2 W4 = *reinterpret_cast<const __half2*>(&wq1.x);
        __half2 W5 = *reinterpret_cast<const __half2*>(&wq1.y);
        __half2 W6 = *reinterpret_cast<const __half2*>(&wq1.z);
        __half2 W7 = *reinterpret_cast<const __half2*>(&wq1.w);

        __half2 a0, a1, a2, a3;
        a0 = __hmul2(*reinterpret_cast<const __half2*>(&v0.x), W0);
        a1 = __hmul2(*reinterpret_cast<const __half2*>(&v0.y), W0);
        a2 = __hmul2(*reinterpret_cast<const __half2*>(&v0.z), W0);
        a3 = __hmul2(*reinterpret_cast<const __half2*>(&v0.w), W0);
        a0 = __hfma2(*reinterpret_cast<const __half2*>(&v1.x), W1, a0);
        a1 = __hfma2(*reinterpret_cast<const __half2*>(&v1.y), W1, a1);
        a2 = __hfma2(*reinterpret_cast<const __half2*>(&v1.z), W1, a2);
        a3 = __hfma2(*reinterpret_cast<const __half2*>(&v1.w), W1, a3);
        a0 = __hfma2(*reinterpret_cast<const __half2*>(&v2.x), W2, a0);
        a1 = __hfma2(*reinterpret_cast<const __half2*>(&v2.y), W2, a1);
        a2 = __hfma2(*reinterpret_cast<const __half2*>(&v2.z), W2, a2);
        a3 = __hfma2(*reinterpret_cast<const __half2*>(&v2.w), W2, a3);
        a0 = __hfma2(*reinterpret_cast<const __half2*>(&v3.x), W3, a0);
        a1 = __hfma2(*reinterpret_cast<const __half2*>(&v3.y), W3, a1);
        a2 = __hfma2(*reinterpret_cast<const __half2*>(&v3.z), W3, a2);
        a3 = __hfma2(*reinterpret_cast<const __half2*>(&v3.w), W3, a3);
        a0 = __hfma2(*reinterpret_cast<const __half2*>(&v4.x), W4, a0);
        a1 = __hfma2(*reinterpret_cast<const __half2*>(&v4.y), W4, a1);
        a2 = __hfma2(*reinterpret_cast<const __half2*>(&v4.z), W4, a2);
        a3 = __hfma2(*reinterpret_cast<const __half2*>(&v4.w), W4, a3);
        a0 = __hfma2(*reinterpret_cast<const __half2*>(&v5.x), W5, a0);
        a1 = __hfma2(*reinterpret_cast<const __half2*>(&v5.y), W5, a1);
        a2 = __hfma2(*reinterpret_cast<const __half2*>(&v5.z), W5, a2);
        a3 = __hfma2(*reinterpret_cast<const __half2*>(&v5.w), W5, a3);
        a0 = __hfma2(*reinterpret_cast<const __half2*>(&v6.x), W6, a0);
        a1 = __hfma2(*reinterpret_cast<const __half2*>(&v6.y), W6, a1);
        a2 = __hfma2(*reinterpret_cast<const __half2*>(&v6.z), W6, a2);
        a3 = __hfma2(*reinterpret_cast<const __half2*>(&v6.w), W6, a3);
        a0 = __hfma2(*reinterpret_cast<const __half2*>(&v7.x), W7, a0);
        a1 = __hfma2(*reinterpret_cast<const __half2*>(&v7.y), W7, a1);
        a2 = __hfma2(*reinterpret_cast<const __half2*>(&v7.z), W7, a2);
        a3 = __hfma2(*reinterpret_cast<const __half2*>(&v7.w), W7, a3);

        // Park packed partials: lane's 4 ch-pairs, one STS.128, conflict-free.
        uint4 pk;
        pk.x = *reinterpret_cast<unsigned*>(&a0);
        pk.y = *reinterpret_cast<unsigned*>(&a1);
        pk.z = *reinterpret_cast<unsigned*>(&a2);
        pk.w = *reinterpret_cast<unsigned*>(&a3);
        *reinterpret_cast<uint4*>(&stageH[sy][bxi][lane * 4]) = pk;
    }
    __syncthreads();

    // Writeout: lanes cover consecutive (c*7 + bx) -> coalesced STG.
    float* orow = out + (size_t)n * (C_CH * NBIN) + by * 7;
    #pragma unroll
    for (int j = t; j < C_CH * 7; j += 64) {
        int c  = j / 7;
        int bx = j - c * 7;
        unsigned u0 = stageH[0][bx][c >> 1];
        unsigned u1 = stageH[1][bx][c >> 1];
        float2 f0 = __half22float2(*reinterpret_cast<__half2*>(&u0));
        float2 f1 = __half22float2(*reinterpret_cast<__half2*>(&u1));
        float v = (c & 1) ? (f0.y + f1.y) : (f0.x + f1.x);
        orow[c * NBIN + bx] = v * 0.25f;
    }
}

extern "C" void kernel_launch(void* const* d_in, const int* in_sizes, int n_in,
                              void* d_out, int out_size) {
    const float* f0    = (const float*)d_in[0];
    const float* f1    = (const float*)d_in[1];
    const float* f2    = (const float*)d_in[2];
    const float* f3    = (const float*)d_in[3];
    const float* props = (const float*)d_in[4];

    int B  = in_sizes[0] / (C_CH * 200 * 200);
    int Np = in_sizes[4] / (4 * B);
    int Nb = B * Np;

    int total = 0;
    const int HWs[4] = {200 * 200, 100 * 100, 50 * 50, 25 * 25};
    for (int l = 0; l < 4; ++l)
        total += ((HWs[l] + 31) / 32) * (C_CH / 64) * B;

    dim3 blk(32, 8);
    transpose_all<<<total, blk>>>(f0, f1, f2, f3, B);

    dim3 grd(Nb, 7);
    roi_main<<<grd, 64>>>(props, (float*)d_out, Np);
}

// round 7
// speedup vs baseline: 1.4540x; 1.4540x over previous
#include <cuda_runtime.h>
#include <cuda_fp16.h>
#include <math.h>

#define C_CH 256
#define NBIN 49

// Channels-last fp16 scratch for the 4 FPN levels (B=2 fixed by problem).
__device__ __half g_h0[2 * 200 * 200 * C_CH];
__device__ __half g_h1[2 * 100 * 100 * C_CH];
__device__ __half g_h2[2 * 50  * 50  * C_CH];
__device__ __half g_h3[2 * 25  * 25  * C_CH];

// Fused transpose: [B,C,HW] fp32 -> [B,HW,C] fp16, all 4 levels in ONE launch.
// Tile = 64ch x 32px per block (256 threads).
// Phase A: LDG.128 (4 px) -> 4x STS.32 into fp32 tile [32px][68].
// Phase B: LDS.128 (4 ch)  -> 2x F2FP.PACK -> STG.64. ~2.25 instr/element.
// NOTE: LDG.128 path requires HW % 4 == 0 (row-base 16B alignment); level 3
// (HW=625) takes the scalar fallback.
__global__ __launch_bounds__(256) void transpose_all(const float* __restrict__ f0,
                                                     const float* __restrict__ f1,
                                                     const float* __restrict__ f2,
                                                     const float* __restrict__ f3,
                                                     int B) {
    __shared__ __align__(16) float tile[32][68];

    const int HWs[4] = {200 * 200, 100 * 100, 50 * 50, 25 * 25};
    int idx = blockIdx.x;
    int l = 0, nPx = 0;
    #pragma unroll
    for (int q = 0; q < 4; ++q) {
        nPx = (HWs[q] + 31) / 32;
        int nb = nPx * (C_CH / 64) * B;
        if (idx < nb) { l = q; break; }
        idx -= nb;
    }
    int HW = HWs[l];
    const float* in = (l == 0) ? f0 : (l == 1) ? f1 : (l == 2) ? f2 : f3;
    __half* outp    = (l == 0) ? g_h0 : (l == 1) ? g_h1 : (l == 2) ? g_h2 : g_h3;

    int pt = idx % nPx;
    int r  = idx / nPx;
    int cg = r % (C_CH / 64);
    int b  = r / (C_CH / 64);

    int p0 = pt * 32;
    int c0 = cg * 64;
    const float* ib = in   + (size_t)b * C_CH * HW;
    __half*      ob = outp + (size_t)b * C_CH * HW;
    int t = threadIdx.x;

    // Phase A: thread t -> px group g = t%8 (4 px), ch row = t/8 (+32 on 2nd pass)
    {
        int g  = t & 7;
        int ch = t >> 3;          // 0..31
        int p  = p0 + 4 * g;
        // Vector path needs tile fully inside AND 16B-aligned row bases:
        // byte offset = (c*HW + p)*4; p % 4 == 0 always, so require HW % 4 == 0.
        bool full = (p0 + 32 <= HW) && ((HW & 3) == 0);
        #pragma unroll
        for (int pass = 0; pass < 2; ++pass) {
            int c = ch + pass * 32;
            const float* src = ib + (size_t)(c0 + c) * HW + p;
            if (full) {
                float4 v = __ldcs((const float4*)src);
                tile[4 * g + 0][c] = v.x;
                tile[4 * g + 1][c] = v.y;
                tile[4 * g + 2][c] = v.z;
                tile[4 * g + 3][c] = v.w;
            } else {
                #pragma unroll
                for (int k = 0; k < 4; ++k)
                    tile[4 * g + k][c] = (p + k < HW) ? __ldcs(src + k) : 0.0f;
            }
        }
    }
    __syncthreads();

    // Phase B: warp w, lane l. Each warp-op covers 2 px x 64 ch.
    {
        int lane = t & 31;
        int w    = t >> 5;        // 0..7
        int cq   = lane & 15;     // 4-ch group
        int ph   = lane >> 4;     // 0/1 px within pair
        #pragma unroll
        for (int j = 0; j < 2; ++j) {
            int px = w * 4 + j * 2 + ph;    // 0..31
            int pg = p0 + px;
            if (pg < HW) {
                float4 v = *reinterpret_cast<const float4*>(&tile[px][4 * cq]);
                __half2 h0 = __floats2half2_rn(v.x, v.y);
                __half2 h1 = __floats2half2_rn(v.z, v.w);
                uint2 pk;
                pk.x = *reinterpret_cast<unsigned*>(&h0);
                pk.y = *reinterpret_cast<unsigned*>(&h1);
                *reinterpret_cast<uint2*>(ob + (size_t)pg * C_CH + c0 + 4 * cq) = pk;
            }
        }
    }
}

// One 64-thread block per (box, output-row). Thread t owns channels {4t..4t+3}
// via one uint2 (= 2x half2) load per tap. All tap offsets/weights precomputed
// once per block into smem as uint4 (LDS.128 in the hot loop). Bilinear combine
// per 2x2-sample group done in HFMA2; fp32 accumulation across groups.
__global__ __launch_bounds__(64, 20) void roi_main(const float* __restrict__ props,
                                                   float* __restrict__ out,
                                                   int Np) {
    __shared__ __align__(16) float stage[7 * 260];   // [bx][c], stride 260
    __shared__ uint4 s_off[28];   // [bxi*4+g] -> 4 tap pixel-offsets (uint2 units)
    __shared__ uint4 s_w[28];     // [bxi*4+g] -> 4 duplicated-half2 weights
    __shared__ int   s_xlo[14], s_xhi[14];
    __shared__ float s_xfr[14], s_xva[14];
    __shared__ int   s_ylo[2],  s_yhi[2];
    __shared__ float s_yfr[2],  s_yva[2];

    int n  = blockIdx.x;
    int by = blockIdx.y;
    int t  = threadIdx.x;

    float bx0 = props[n * 4 + 0];
    float by0 = props[n * 4 + 1];
    float bx1 = props[n * 4 + 2];
    float by1 = props[n * 4 + 3];

    float s  = sqrtf((bx1 - bx0) * (by1 - by0));
    float lv = floorf(4.0f + log2f(s * (1.0f / 224.0f) + 1e-6f));
    lv = fminf(fmaxf(lv, 2.0f), 5.0f);
    int l = (int)lv - 2;

    int H;
    float scale;
    const __half* fp;
    if      (l == 0) { H = 200; scale = 0.25f;    fp = g_h0; }
    else if (l == 1) { H = 100; scale = 0.125f;   fp = g_h1; }
    else if (l == 2) { H = 50;  scale = 0.0625f;  fp = g_h2; }
    else             { H = 25;  scale = 0.03125f; fp = g_h3; }
    int W = H;
    int bidx = n / Np;

    // Sample prep: threads 0..13 -> x samples, 14..15 -> the 2 y samples of this row.
    if (t < 16) {
        bool isY = (t >= 14);
        int  k   = isY ? (2 * by + (t - 14)) : t;
        float off = (float)(k >> 1) + ((float)(k & 1) + 0.5f) * 0.5f;
        float c0  = (isY ? by0 : bx0) * scale;
        float c1  = (isY ? by1 : bx1) * scale;
        float bin = fmaxf(c1 - c0, 1.0f) * (1.0f / 7.0f);
        float c   = c0 + off * bin;
        float valid = (c >= -1.0f && c <= (float)H) ? 1.0f : 0.0f;
        float cc  = fmaxf(c, 0.0f);
        int   lo0 = (int)floorf(cc);
        bool  edge = (lo0 >= H - 1);
        int lo = edge ? (H - 1) : lo0;
        int hi = edge ? (H - 1) : (lo0 + 1);
        float fr = edge ? 0.0f : (cc - (float)lo0);
        if (isY) { int q = t - 14; s_ylo[q] = lo; s_yhi[q] = hi; s_yfr[q] = fr; s_yva[q] = valid; }
        else     {                 s_xlo[t] = lo; s_xhi[t] = hi; s_xfr[t] = fr; s_xva[t] = valid; }
    }
    __syncthreads();

    // Precompute 112 taps: i = bxi*16 + g*4 + tap; g = (sy,sx) group.
    #pragma unroll
    for (int i = t; i < 112; i += 64) {
        int bxi = i >> 4, r = i & 15, g = r >> 2, tap = r & 3;
        int sy = g >> 1, sx = g & 1;
        int kx = 2 * bxi + sx;
        int row = (tap & 2) ? s_yhi[sy] : s_ylo[sy];
        int x   = (tap & 1) ? s_xhi[kx] : s_xlo[kx];
        float wy = (tap & 2) ? s_yfr[sy] : (1.0f - s_yfr[sy]);
        float wx = (tap & 1) ? s_xfr[kx] : (1.0f - s_xfr[kx]);
        float w  = s_yva[sy] * s_xva[kx] * wy * wx;
        ((unsigned*)s_off)[i] = (unsigned)((row * W + x) * (C_CH / 4));
        unsigned hb = (unsigned)__half_as_ushort(__float2half_rn(w));
        ((unsigned*)s_w)[i] = hb | (hb << 16);
    }
    __syncthreads();

    const uint2* fb = (const uint2*)(fp + (size_t)bidx * H * W * C_CH) + t;

    #pragma unroll 1
    for (int bxi = 0; bxi < 7; ++bxi) {
        float r0 = 0.0f, r1 = 0.0f, r2 = 0.0f, r3 = 0.0f;
        #pragma unroll
        for (int g = 0; g < 4; ++g) {
            uint4 off = s_off[bxi * 4 + g];
            uint4 wq  = s_w[bxi * 4 + g];
            uint2 v0 = __ldg(fb + off.x);
            uint2 v1 = __ldg(fb + off.y);
            uint2 v2 = __ldg(fb + off.z);
            uint2 v3 = __ldg(fb + off.w);
            __half2 w0 = *reinterpret_cast<const __half2*>(&wq.x);
            __half2 w1 = *reinterpret_cast<const __half2*>(&wq.y);
            __half2 w2 = *reinterpret_cast<const __half2*>(&wq.z);
            __half2 w3 = *reinterpret_cast<const __half2*>(&wq.w);
            __half2 aL = __hmul2(*reinterpret_cast<const __half2*>(&v0.x), w0);
            __half2 aH = __hmul2(*reinterpret_cast<const __half2*>(&v0.y), w0);
            aL = __hfma2(*reinterpret_cast<const __half2*>(&v1.x), w1, aL);
            aH = __hfma2(*reinterpret_cast<const __half2*>(&v1.y), w1, aH);
            aL = __hfma2(*reinterpret_cast<const __half2*>(&v2.x), w2, aL);
            aH = __hfma2(*reinterpret_cast<const __half2*>(&v2.y), w2, aH);
            aL = __hfma2(*reinterpret_cast<const __half2*>(&v3.x), w3, aL);
            aH = __hfma2(*reinterpret_cast<const __half2*>(&v3.y), w3, aH);
            float2 fL = __half22float2(aL);
            float2 fH = __half22float2(aH);
            r0 += fL.x; r1 += fL.y; r2 += fH.x; r3 += fH.y;
        }
        *reinterpret_cast<float4*>(&stage[bxi * 260 + 4 * t]) =
            make_float4(r0 * 0.25f, r1 * 0.25f, r2 * 0.25f, r3 * 0.25f);
    }
    __syncthreads();

    // Write this row: out[n, c, by, bx] for all c, bx. j = c*7 + bx keeps
    // global writes contiguous across lanes.
    float* orow = out + (size_t)n * (C_CH * NBIN) + by * 7;
    #pragma unroll
    for (int j = t; j < C_CH * 7; j += 64) {
        int c  = j / 7;
        int bx = j - c * 7;
        orow[c * NBIN + bx] = stage[bx * 260 + c];
    }
}

extern "C" void kernel_launch(void* const* d_in, const int* in_sizes, int n_in,
                              void* d_out, int out_size) {
    const float* f0    = (const float*)d_in[0];
    const float* f1    = (const float*)d_in[1];
    const float* f2    = (const float*)d_in[2];
    const float* f3    = (const float*)d_in[3];
    const float* props = (const float*)d_in[4];

    int B  = in_sizes[0] / (C_CH * 200 * 200);
    int Np = in_sizes[4] / (4 * B);
    int Nb = B * Np;

    int total = 0;
    const int HWs[4] = {200 * 200, 100 * 100, 50 * 50, 25 * 25};
    for (int l = 0; l < 4; ++l)
        total += ((HWs[l] + 31) / 32) * (C_CH / 64) * B;

    transpose_all<<<total, 256>>>(f0, f1, f2, f3, B);

    dim3 grd(Nb, 7);
    roi_main<<<grd, 64>>>(props, (float*)d_out, Np);
}